// round 1
// baseline (speedup 1.0000x reference)
#include <cuda_runtime.h>
#include <math.h>
#include <float.h>

// Problem constants
#define NSEQ 2048
#define DMODEL 1024
#define NHEADS 16
#define HDIM 64
#define D3 3072

// ---------------- device scratch (static, no allocation) ----------------
__device__ float g_Q[NHEADS * NSEQ * HDIM];
__device__ float g_K[NHEADS * NSEQ * HDIM];
__device__ float g_V[NHEADS * NSEQ * HDIM];
__device__ float g_pq[NHEADS * NSEQ * 3];
__device__ float g_pk[NHEADS * NSEQ * 3];
__device__ float g_sqq[NHEADS * NSEQ];
__device__ float g_sqk[NHEADS * NSEQ];
__device__ float g_m[NHEADS * NSEQ];
__device__ float g_l[NHEADS * NSEQ];
__device__ float g_att[NSEQ * DMODEL];
__device__ float g_res[NSEQ * DMODEL];
__device__ float g_W[(size_t)NHEADS * NSEQ * NSEQ];  // 256 MB per-head attention weights

// ---------------- generic 128x128x16 SGEMM, 256 threads, 8x8/thread ----------------
// MODE 0: C = A@B + bias, scattered into g_Q/g_K/g_V (qkv layout split)
// MODE 1: g_res = A@B + bias + resid
template <int MODE>
__global__ void sgemm128(const float* __restrict__ A, const float* __restrict__ B,
                         const float* __restrict__ bias, const float* __restrict__ resid,
                         int Ncols, int K) {
    __shared__ float As[16][128];
    __shared__ float Bs[16][128];
    const int row0 = blockIdx.y * 128;
    const int col0 = blockIdx.x * 128;
    const int tid = threadIdx.x;
    const int tr = tid / 16, tc = tid % 16;

    float acc[8][8];
#pragma unroll
    for (int u = 0; u < 8; u++)
#pragma unroll
        for (int v = 0; v < 8; v++) acc[u][v] = 0.f;

    for (int k0 = 0; k0 < K; k0 += 16) {
        // A tile: 128 rows x 16 cols, store transposed As[k][row]
#pragma unroll
        for (int r = 0; r < 2; r++) {
            int idx = tid + r * 256;           // 0..511
            int ar = idx >> 2, k4 = idx & 3;   // row, float4-group
            float4 v = *(const float4*)(A + (size_t)(row0 + ar) * K + k0 + k4 * 4);
            As[k4 * 4 + 0][ar] = v.x;
            As[k4 * 4 + 1][ar] = v.y;
            As[k4 * 4 + 2][ar] = v.z;
            As[k4 * 4 + 3][ar] = v.w;
        }
        // B tile: 16 rows x 128 cols
#pragma unroll
        for (int r = 0; r < 2; r++) {
            int idx = tid + r * 256;
            int kk = idx >> 5, j4 = idx & 31;
            *(float4*)(&Bs[kk][j4 * 4]) =
                *(const float4*)(B + (size_t)(k0 + kk) * Ncols + col0 + j4 * 4);
        }
        __syncthreads();
#pragma unroll
        for (int kk = 0; kk < 16; kk++) {
            float a[8], b[8];
#pragma unroll
            for (int u = 0; u < 8; u++) a[u] = As[kk][tr * 8 + u];
#pragma unroll
            for (int v = 0; v < 8; v++) b[v] = Bs[kk][tc * 8 + v];
#pragma unroll
            for (int u = 0; u < 8; u++)
#pragma unroll
                for (int v = 0; v < 8; v++) acc[u][v] = fmaf(a[u], b[v], acc[u][v]);
        }
        __syncthreads();
    }

#pragma unroll
    for (int u = 0; u < 8; u++) {
        int n = row0 + tr * 8 + u;
#pragma unroll
        for (int v = 0; v < 8; v++) {
            int c = col0 + tc * 8 + v;
            float val = acc[u][v] + bias[c];
            if (MODE == 0) {
                int which = c >> 10;           // 0:q 1:k 2:v
                int h = (c >> 6) & 15;
                int d = c & 63;
                float* dst = (which == 0) ? g_Q : (which == 1) ? g_K : g_V;
                dst[((size_t)h * NSEQ + n) * HDIM + d] = val;
            } else {
                g_res[(size_t)n * DMODEL + c] = val + resid[(size_t)n * DMODEL + c];
            }
        }
    }
}

// ---------------- point projections: pq = x@Wpq+b, pk = x@Wpk+b, plus |.|^2 ----------------
__global__ void point_proj_kernel(const float* __restrict__ x,
                                  const float* __restrict__ Wpq, const float* __restrict__ bpq,
                                  const float* __restrict__ Wpk, const float* __restrict__ bpk) {
    __shared__ float xs[DMODEL];
    __shared__ float outs[96];
    const int n = blockIdx.x;
    for (int i = threadIdx.x; i < DMODEL; i += blockDim.x) xs[i] = x[(size_t)n * DMODEL + i];
    __syncthreads();
    const int t = threadIdx.x;
    if (t < 96) {
        const bool isq = t < 48;
        const int c = isq ? t : t - 48;
        const float* W = isq ? Wpq : Wpk;
        float s = isq ? bpq[c] : bpk[c];
#pragma unroll 8
        for (int k = 0; k < DMODEL; k++) s = fmaf(xs[k], W[k * 48 + c], s);
        outs[t] = s;
        int h = c / 3, comp = c % 3;
        float* dst = isq ? g_pq : g_pk;
        dst[((size_t)h * NSEQ + n) * 3 + comp] = s;
    }
    __syncthreads();
    if (t < 32) {
        int h = t & 15;
        bool isq = t < 16;
        const float* src = isq ? outs : outs + 48;
        float a = src[h * 3], b = src[h * 3 + 1], cc = src[h * 3 + 2];
        (isq ? g_sqq : g_sqk)[(size_t)h * NSEQ + n] = a * a + b * b + cc * cc;
    }
}

// ---------------- attention pass 1: per-row softmax max & sum ----------------
// grid (16 qtiles, 16 heads), 256 threads, dyn smem
__global__ void attn_pass1(const unsigned char* __restrict__ mask) {
    extern __shared__ float sm[];
    float* Qs = sm;                    // 64*129
    float* Ks = Qs + 64 * 129;         // 64*129
    float* qm = Ks + 64 * 129;         // 128*4
    float* km = qm + 512;              // 128*4
    float* kmask = km + 512;           // 128
    float* red = kmask + 128;          // 128*16
    float* s_m = red + 2048;           // 128
    float* s_l = s_m + 128;            // 128
    float* s_mn = s_l + 128;           // 128

    const int q0 = blockIdx.x * 128;
    const int h = blockIdx.y;
    const int tid = threadIdx.x;
    const int tr = tid / 16, tc = tid % 16;
    const int i0 = tr * 8, j0 = tc * 8;

    const float* Qg = g_Q + ((size_t)h * NSEQ + q0) * HDIM;
    for (int idx = tid; idx < 128 * 64; idx += 256) {
        int d = idx & 63, i = idx >> 6;
        Qs[d * 129 + i] = Qg[(size_t)i * HDIM + d];
    }
    if (tid < 128) {
        int n = q0 + tid;
        const float* p = g_pq + ((size_t)h * NSEQ + n) * 3;
        qm[tid * 4 + 0] = p[0];
        qm[tid * 4 + 1] = p[1];
        qm[tid * 4 + 2] = p[2];
        qm[tid * 4 + 3] = g_sqq[(size_t)h * NSEQ + n];
        s_m[tid] = -INFINITY;
        s_l[tid] = 0.f;
    }

    for (int k0 = 0; k0 < NSEQ; k0 += 128) {
        __syncthreads();  // previous iter reads done / Q load done
        const float* Kg = g_K + ((size_t)h * NSEQ + k0) * HDIM;
        for (int idx = tid; idx < 128 * 64; idx += 256) {
            int d = idx & 63, j = idx >> 6;
            Ks[d * 129 + j] = Kg[(size_t)j * HDIM + d];
        }
        if (tid < 128) {
            int m = k0 + tid;
            const float* p = g_pk + ((size_t)h * NSEQ + m) * 3;
            km[tid * 4 + 0] = p[0];
            km[tid * 4 + 1] = p[1];
            km[tid * 4 + 2] = p[2];
            km[tid * 4 + 3] = g_sqk[(size_t)h * NSEQ + m];
            kmask[tid] = mask[m] ? 1.f : 0.f;
        }
        __syncthreads();

        float s[8][8];
#pragma unroll
        for (int u = 0; u < 8; u++)
#pragma unroll
            for (int v = 0; v < 8; v++) s[u][v] = 0.f;
#pragma unroll 4
        for (int d = 0; d < 64; d++) {
            float a[8], b[8];
#pragma unroll
            for (int u = 0; u < 8; u++) a[u] = Qs[d * 129 + i0 + u];
#pragma unroll
            for (int v = 0; v < 8; v++) b[v] = Ks[d * 129 + j0 + v];
#pragma unroll
            for (int u = 0; u < 8; u++)
#pragma unroll
                for (int v = 0; v < 8; v++) s[u][v] = fmaf(a[u], b[v], s[u][v]);
        }
#pragma unroll
        for (int u = 0; u < 8; u++) {
            const float pq0 = qm[(i0 + u) * 4 + 0];
            const float pq1 = qm[(i0 + u) * 4 + 1];
            const float pq2 = qm[(i0 + u) * 4 + 2];
            const float sqq = qm[(i0 + u) * 4 + 3];
            float tmax = -INFINITY;
#pragma unroll
            for (int v = 0; v < 8; v++) {
                float cross = pq0 * km[(j0 + v) * 4 + 0] + pq1 * km[(j0 + v) * 4 + 1] +
                              pq2 * km[(j0 + v) * 4 + 2];
                float sv = s[u][v] * 0.125f + sqq + km[(j0 + v) * 4 + 3] - 2.f * cross;
                if (kmask[j0 + v] != 0.f) sv = -INFINITY;
                s[u][v] = sv;
                tmax = fmaxf(tmax, sv);
            }
            red[(i0 + u) * 16 + tc] = tmax;
        }
        __syncthreads();
        if (tid < 128) {
            float mn = s_m[tid];
#pragma unroll
            for (int c = 0; c < 16; c++) mn = fmaxf(mn, red[tid * 16 + c]);
            s_mn[tid] = mn;
        }
        __syncthreads();
#pragma unroll
        for (int u = 0; u < 8; u++) {
            float mn = s_mn[i0 + u];
            float ps = 0.f;
            if (mn != -INFINITY) {
#pragma unroll
                for (int v = 0; v < 8; v++) ps += __expf(s[u][v] - mn);
            }
            red[(i0 + u) * 16 + tc] = ps;
        }
        __syncthreads();
        if (tid < 128) {
            float mo = s_m[tid], mn = s_mn[tid];
            float l = s_l[tid];
            float scale = (mo == -INFINITY) ? 0.f : __expf(mo - mn);
            l *= scale;
#pragma unroll
            for (int c = 0; c < 16; c++) l += red[tid * 16 + c];
            s_l[tid] = l;
            s_m[tid] = mn;
        }
    }
    __syncthreads();
    if (tid < 128) {
        g_m[(size_t)h * NSEQ + q0 + tid] = s_m[tid];
        g_l[(size_t)h * NSEQ + q0 + tid] = s_l[tid];
    }
}

// ---------------- attention pass 2: normalized w -> g_W, attended = w@V ----------------
__global__ void attn_pass2(const unsigned char* __restrict__ mask) {
    extern __shared__ float sm[];
    float* Qs = sm;                    // 64*129 = 8256
    float* Ks = Qs + 8256;             // 8256
    float* Vs = Ks + 8256;             // 128*68 = 8704
    float* Ps = Vs + 8704;             // 128*129 = 16512
    float* qm = Ps + 16512;            // 512
    float* km = qm + 512;              // 512
    float* kmask = km + 512;           // 128
    float* s_m = kmask + 128;          // 128
    float* s_li = s_m + 128;           // 128

    const int q0 = blockIdx.x * 128;
    const int h = blockIdx.y;
    const int tid = threadIdx.x;
    const int tr = tid / 16, tc = tid % 16;
    const int i0 = tr * 8, j0 = tc * 8;
    const int ib0 = tr * 8, d0 = tc * 4;  // AV roles

    const float* Qg = g_Q + ((size_t)h * NSEQ + q0) * HDIM;
    for (int idx = tid; idx < 128 * 64; idx += 256) {
        int d = idx & 63, i = idx >> 6;
        Qs[d * 129 + i] = Qg[(size_t)i * HDIM + d];
    }
    if (tid < 128) {
        int n = q0 + tid;
        const float* p = g_pq + ((size_t)h * NSEQ + n) * 3;
        qm[tid * 4 + 0] = p[0];
        qm[tid * 4 + 1] = p[1];
        qm[tid * 4 + 2] = p[2];
        qm[tid * 4 + 3] = g_sqq[(size_t)h * NSEQ + n];
        s_m[tid] = g_m[(size_t)h * NSEQ + n];
        float l = g_l[(size_t)h * NSEQ + n];
        s_li[tid] = (l > 0.f) ? 1.f / l : 0.f;
    }

    float acc[8][4];
#pragma unroll
    for (int u = 0; u < 8; u++)
#pragma unroll
        for (int c = 0; c < 4; c++) acc[u][c] = 0.f;

    for (int k0 = 0; k0 < NSEQ; k0 += 128) {
        __syncthreads();  // previous AV reads done
        const float* Kg = g_K + ((size_t)h * NSEQ + k0) * HDIM;
        const float* Vg = g_V + ((size_t)h * NSEQ + k0) * HDIM;
        for (int idx = tid; idx < 128 * 64; idx += 256) {
            int d = idx & 63, j = idx >> 6;
            Ks[d * 129 + j] = Kg[(size_t)j * HDIM + d];
            Vs[j * 68 + d] = Vg[(size_t)j * HDIM + d];
        }
        if (tid < 128) {
            int m = k0 + tid;
            const float* p = g_pk + ((size_t)h * NSEQ + m) * 3;
            km[tid * 4 + 0] = p[0];
            km[tid * 4 + 1] = p[1];
            km[tid * 4 + 2] = p[2];
            km[tid * 4 + 3] = g_sqk[(size_t)h * NSEQ + m];
            kmask[tid] = mask[m] ? 1.f : 0.f;
        }
        __syncthreads();

        float s[8][8];
#pragma unroll
        for (int u = 0; u < 8; u++)
#pragma unroll
            for (int v = 0; v < 8; v++) s[u][v] = 0.f;
#pragma unroll 4
        for (int d = 0; d < 64; d++) {
            float a[8], b[8];
#pragma unroll
            for (int u = 0; u < 8; u++) a[u] = Qs[d * 129 + i0 + u];
#pragma unroll
            for (int v = 0; v < 8; v++) b[v] = Ks[d * 129 + j0 + v];
#pragma unroll
            for (int u = 0; u < 8; u++)
#pragma unroll
                for (int v = 0; v < 8; v++) s[u][v] = fmaf(a[u], b[v], s[u][v]);
        }
#pragma unroll
        for (int u = 0; u < 8; u++) {
            const float pq0 = qm[(i0 + u) * 4 + 0];
            const float pq1 = qm[(i0 + u) * 4 + 1];
            const float pq2 = qm[(i0 + u) * 4 + 2];
            const float sqq = qm[(i0 + u) * 4 + 3];
            const float mrow = s_m[i0 + u];
            const float lirow = s_li[i0 + u];
#pragma unroll
            for (int v = 0; v < 8; v++) {
                float cross = pq0 * km[(j0 + v) * 4 + 0] + pq1 * km[(j0 + v) * 4 + 1] +
                              pq2 * km[(j0 + v) * 4 + 2];
                float sv = s[u][v] * 0.125f + sqq + km[(j0 + v) * 4 + 3] - 2.f * cross;
                float P;
                if (kmask[j0 + v] != 0.f || mrow == -INFINITY)
                    P = 0.f;
                else
                    P = __expf(sv - mrow) * lirow;
                Ps[(j0 + v) * 129 + (i0 + u)] = P;
                g_W[((size_t)h * NSEQ + (q0 + i0 + u)) * NSEQ + (k0 + j0 + v)] = P;
            }
        }
        __syncthreads();
        // AV: acc[i][d] += sum_j Ps[j][i] * Vs[j][d]
#pragma unroll 2
        for (int j = 0; j < 128; j++) {
            float4 vv = *(const float4*)&Vs[j * 68 + d0];
#pragma unroll
            for (int u = 0; u < 8; u++) {
                float p = Ps[j * 129 + ib0 + u];
                acc[u][0] = fmaf(p, vv.x, acc[u][0]);
                acc[u][1] = fmaf(p, vv.y, acc[u][1]);
                acc[u][2] = fmaf(p, vv.z, acc[u][2]);
                acc[u][3] = fmaf(p, vv.w, acc[u][3]);
            }
        }
    }
#pragma unroll
    for (int u = 0; u < 8; u++) {
        int n = q0 + ib0 + u;
#pragma unroll
        for (int c = 0; c < 4; c++)
            g_att[(size_t)n * DMODEL + h * HDIM + d0 + c] = acc[u][c];
    }
}

// ---------------- mean over heads of attention weights ----------------
__global__ void meanw_kernel(float* __restrict__ meanw) {
    size_t idx = (size_t)blockIdx.x * blockDim.x + threadIdx.x;
    if (idx < (size_t)NSEQ * NSEQ) {
        float s = 0.f;
#pragma unroll
        for (int h = 0; h < NHEADS; h++) s += g_W[(size_t)h * NSEQ * NSEQ + idx];
        meanw[idx] = s * (1.f / NHEADS);
    }
}

// ---------------- layernorm over g_res ----------------
__global__ void ln_kernel(const float* __restrict__ gamma, const float* __restrict__ beta,
                          float* __restrict__ out) {
    const int n = blockIdx.x;
    const int tid = threadIdx.x;
    __shared__ float sred[256];
    __shared__ float s_mu, s_rstd;
    const float* r = g_res + (size_t)n * DMODEL;
    float v[4];
    float s = 0.f;
#pragma unroll
    for (int k = 0; k < 4; k++) {
        v[k] = r[tid + k * 256];
        s += v[k];
    }
    sred[tid] = s;
    __syncthreads();
    for (int off = 128; off > 0; off >>= 1) {
        if (tid < off) sred[tid] += sred[tid + off];
        __syncthreads();
    }
    if (tid == 0) s_mu = sred[0] * (1.f / DMODEL);
    __syncthreads();
    const float mu = s_mu;
    float s2 = 0.f;
#pragma unroll
    for (int k = 0; k < 4; k++) {
        float d = v[k] - mu;
        s2 += d * d;
    }
    sred[tid] = s2;
    __syncthreads();
    for (int off = 128; off > 0; off >>= 1) {
        if (tid < off) sred[tid] += sred[tid + off];
        __syncthreads();
    }
    if (tid == 0) s_rstd = rsqrtf(sred[0] * (1.f / DMODEL) + 1e-5f);
    __syncthreads();
    const float rstd = s_rstd;
#pragma unroll
    for (int k = 0; k < 4; k++) {
        int c = tid + k * 256;
        out[(size_t)n * DMODEL + c] = (v[k] - mu) * rstd * gamma[c] + beta[c];
    }
}

// ---------------- host ----------------
#define P1_SMEM (20096 * 4)
#define P2_SMEM (43136 * 4)

extern "C" void kernel_launch(void* const* d_in, const int* in_sizes, int n_in,
                              void* d_out, int out_size) {
    const float* x = (const float*)d_in[0];
    // d_in[1] = positions (unused by the reference forward)
    const unsigned char* mask = (const unsigned char*)d_in[2];
    const float* Wqkv = (const float*)d_in[3];
    const float* bqkv = (const float*)d_in[4];
    const float* Wpq = (const float*)d_in[5];
    const float* bpq = (const float*)d_in[6];
    const float* Wpk = (const float*)d_in[7];
    const float* bpk = (const float*)d_in[8];
    const float* Wo = (const float*)d_in[9];
    const float* bo = (const float*)d_in[10];
    const float* gamma = (const float*)d_in[11];
    const float* beta = (const float*)d_in[12];

    float* out = (float*)d_out;
    float* meanw = out + (size_t)NSEQ * DMODEL;

    void* attp = nullptr;
    cudaGetSymbolAddress(&attp, g_att);

    cudaFuncSetAttribute(attn_pass1, cudaFuncAttributeMaxDynamicSharedMemorySize, P1_SMEM);
    cudaFuncSetAttribute(attn_pass2, cudaFuncAttributeMaxDynamicSharedMemorySize, P2_SMEM);

    // 1) fused QKV projection, scattered into per-head Q/K/V
    sgemm128<0><<<dim3(D3 / 128, NSEQ / 128), 256>>>(x, Wqkv, bqkv, nullptr, D3, DMODEL);
    // 2) point projections + squared norms
    point_proj_kernel<<<NSEQ, 128>>>(x, Wpq, bpq, Wpk, bpk);
    // 3) softmax stats
    attn_pass1<<<dim3(NSEQ / 128, NHEADS), 256, P1_SMEM>>>(mask);
    // 4) normalized weights + attended values
    attn_pass2<<<dim3(NSEQ / 128, NHEADS), 256, P2_SMEM>>>(mask);
    // 5) mean over heads -> second output
    meanw_kernel<<<(NSEQ * NSEQ + 255) / 256, 256>>>(meanw);
    // 6) output projection + residual
    sgemm128<1><<<dim3(DMODEL / 128, NSEQ / 128), 256>>>((const float*)attp, Wo, bo, x,
                                                          DMODEL, DMODEL);
    // 7) layernorm -> first output
    ln_kernel<<<NSEQ, 256>>>(gamma, beta, out);
}

// round 2
// speedup vs baseline: 1.0002x; 1.0002x over previous
#include <cuda_runtime.h>
#include <math.h>
#include <float.h>

// Problem constants
#define NSEQ 2048
#define DMODEL 1024
#define NHEADS 16
#define HDIM 64
#define D3 3072

// ---------------- device scratch (static, no allocation) ----------------
__device__ float g_Q[NHEADS * NSEQ * HDIM];
__device__ float g_K[NHEADS * NSEQ * HDIM];
__device__ float g_V[NHEADS * NSEQ * HDIM];
__device__ float g_pq[NHEADS * NSEQ * 3];
__device__ float g_pk[NHEADS * NSEQ * 3];
__device__ float g_sqq[NHEADS * NSEQ];
__device__ float g_sqk[NHEADS * NSEQ];
__device__ float g_m[NHEADS * NSEQ];
__device__ float g_l[NHEADS * NSEQ];
__device__ float g_att[NSEQ * DMODEL];
__device__ float g_res[NSEQ * DMODEL];
__device__ float g_W[(size_t)NHEADS * NSEQ * NSEQ];  // 256 MB per-head attention weights

// ---------------- generic 128x128x16 SGEMM, 256 threads, 8x8/thread ----------------
// MODE 0: C = A@B + bias, scattered into g_Q/g_K/g_V (qkv layout split)
// MODE 1: g_res = A@B + bias + resid
template <int MODE>
__global__ void sgemm128(const float* __restrict__ A, const float* __restrict__ B,
                         const float* __restrict__ bias, const float* __restrict__ resid,
                         int Ncols, int K) {
    __shared__ float As[16][128];
    __shared__ float Bs[16][128];
    const int row0 = blockIdx.y * 128;
    const int col0 = blockIdx.x * 128;
    const int tid = threadIdx.x;
    const int tr = tid / 16, tc = tid % 16;

    float acc[8][8];
#pragma unroll
    for (int u = 0; u < 8; u++)
#pragma unroll
        for (int v = 0; v < 8; v++) acc[u][v] = 0.f;

    for (int k0 = 0; k0 < K; k0 += 16) {
        // A tile: 128 rows x 16 cols, store transposed As[k][row]
#pragma unroll
        for (int r = 0; r < 2; r++) {
            int idx = tid + r * 256;           // 0..511
            int ar = idx >> 2, k4 = idx & 3;   // row, float4-group
            float4 v = *(const float4*)(A + (size_t)(row0 + ar) * K + k0 + k4 * 4);
            As[k4 * 4 + 0][ar] = v.x;
            As[k4 * 4 + 1][ar] = v.y;
            As[k4 * 4 + 2][ar] = v.z;
            As[k4 * 4 + 3][ar] = v.w;
        }
        // B tile: 16 rows x 128 cols
#pragma unroll
        for (int r = 0; r < 2; r++) {
            int idx = tid + r * 256;
            int kk = idx >> 5, j4 = idx & 31;
            *(float4*)(&Bs[kk][j4 * 4]) =
                *(const float4*)(B + (size_t)(k0 + kk) * Ncols + col0 + j4 * 4);
        }
        __syncthreads();
#pragma unroll
        for (int kk = 0; kk < 16; kk++) {
            float a[8], b[8];
#pragma unroll
            for (int u = 0; u < 8; u++) a[u] = As[kk][tr * 8 + u];
#pragma unroll
            for (int v = 0; v < 8; v++) b[v] = Bs[kk][tc * 8 + v];
#pragma unroll
            for (int u = 0; u < 8; u++)
#pragma unroll
                for (int v = 0; v < 8; v++) acc[u][v] = fmaf(a[u], b[v], acc[u][v]);
        }
        __syncthreads();
    }

#pragma unroll
    for (int u = 0; u < 8; u++) {
        int n = row0 + tr * 8 + u;
#pragma unroll
        for (int v = 0; v < 8; v++) {
            int c = col0 + tc * 8 + v;
            float val = acc[u][v] + bias[c];
            if (MODE == 0) {
                int which = c >> 10;           // 0:q 1:k 2:v
                int h = (c >> 6) & 15;
                int d = c & 63;
                float* dst = (which == 0) ? g_Q : (which == 1) ? g_K : g_V;
                dst[((size_t)h * NSEQ + n) * HDIM + d] = val;
            } else {
                g_res[(size_t)n * DMODEL + c] = val + resid[(size_t)n * DMODEL + c];
            }
        }
    }
}

// ---------------- point projections: pq = x@Wpq+b, pk = x@Wpk+b, plus |.|^2 ----------------
__global__ void point_proj_kernel(const float* __restrict__ x,
                                  const float* __restrict__ Wpq, const float* __restrict__ bpq,
                                  const float* __restrict__ Wpk, const float* __restrict__ bpk) {
    __shared__ float xs[DMODEL];
    __shared__ float outs[96];
    const int n = blockIdx.x;
    for (int i = threadIdx.x; i < DMODEL; i += blockDim.x) xs[i] = x[(size_t)n * DMODEL + i];
    __syncthreads();
    const int t = threadIdx.x;
    if (t < 96) {
        const bool isq = t < 48;
        const int c = isq ? t : t - 48;
        const float* W = isq ? Wpq : Wpk;
        float s = isq ? bpq[c] : bpk[c];
#pragma unroll 8
        for (int k = 0; k < DMODEL; k++) s = fmaf(xs[k], W[k * 48 + c], s);
        outs[t] = s;
        int h = c / 3, comp = c % 3;
        float* dst = isq ? g_pq : g_pk;
        dst[((size_t)h * NSEQ + n) * 3 + comp] = s;
    }
    __syncthreads();
    if (t < 32) {
        int h = t & 15;
        bool isq = t < 16;
        const float* src = isq ? outs : outs + 48;
        float a = src[h * 3], b = src[h * 3 + 1], cc = src[h * 3 + 2];
        (isq ? g_sqq : g_sqk)[(size_t)h * NSEQ + n] = a * a + b * b + cc * cc;
    }
}

// ---------------- attention pass 1: per-row softmax max & sum ----------------
// grid (16 qtiles, 16 heads), 256 threads, dyn smem
__global__ void attn_pass1(const unsigned char* __restrict__ mask) {
    extern __shared__ float sm[];
    float* Qs = sm;                    // 64*129
    float* Ks = Qs + 64 * 129;         // 64*129
    float* qm = Ks + 64 * 129;         // 128*4
    float* km = qm + 512;              // 128*4
    float* kmask = km + 512;           // 128
    float* red = kmask + 128;          // 128*16
    float* s_m = red + 2048;           // 128
    float* s_l = s_m + 128;            // 128
    float* s_mn = s_l + 128;           // 128

    const int q0 = blockIdx.x * 128;
    const int h = blockIdx.y;
    const int tid = threadIdx.x;
    const int tr = tid / 16, tc = tid % 16;
    const int i0 = tr * 8, j0 = tc * 8;

    const float* Qg = g_Q + ((size_t)h * NSEQ + q0) * HDIM;
    for (int idx = tid; idx < 128 * 64; idx += 256) {
        int d = idx & 63, i = idx >> 6;
        Qs[d * 129 + i] = Qg[(size_t)i * HDIM + d];
    }
    if (tid < 128) {
        int n = q0 + tid;
        const float* p = g_pq + ((size_t)h * NSEQ + n) * 3;
        qm[tid * 4 + 0] = p[0];
        qm[tid * 4 + 1] = p[1];
        qm[tid * 4 + 2] = p[2];
        qm[tid * 4 + 3] = g_sqq[(size_t)h * NSEQ + n];
        s_m[tid] = -INFINITY;
        s_l[tid] = 0.f;
    }

    for (int k0 = 0; k0 < NSEQ; k0 += 128) {
        __syncthreads();  // previous iter reads done / Q load done
        const float* Kg = g_K + ((size_t)h * NSEQ + k0) * HDIM;
        for (int idx = tid; idx < 128 * 64; idx += 256) {
            int d = idx & 63, j = idx >> 6;
            Ks[d * 129 + j] = Kg[(size_t)j * HDIM + d];
        }
        if (tid < 128) {
            int m = k0 + tid;
            const float* p = g_pk + ((size_t)h * NSEQ + m) * 3;
            km[tid * 4 + 0] = p[0];
            km[tid * 4 + 1] = p[1];
            km[tid * 4 + 2] = p[2];
            km[tid * 4 + 3] = g_sqk[(size_t)h * NSEQ + m];
            kmask[tid] = mask[m] ? 1.f : 0.f;
        }
        __syncthreads();

        float s[8][8];
#pragma unroll
        for (int u = 0; u < 8; u++)
#pragma unroll
            for (int v = 0; v < 8; v++) s[u][v] = 0.f;
#pragma unroll 4
        for (int d = 0; d < 64; d++) {
            float a[8], b[8];
#pragma unroll
            for (int u = 0; u < 8; u++) a[u] = Qs[d * 129 + i0 + u];
#pragma unroll
            for (int v = 0; v < 8; v++) b[v] = Ks[d * 129 + j0 + v];
#pragma unroll
            for (int u = 0; u < 8; u++)
#pragma unroll
                for (int v = 0; v < 8; v++) s[u][v] = fmaf(a[u], b[v], s[u][v]);
        }
#pragma unroll
        for (int u = 0; u < 8; u++) {
            const float pq0 = qm[(i0 + u) * 4 + 0];
            const float pq1 = qm[(i0 + u) * 4 + 1];
            const float pq2 = qm[(i0 + u) * 4 + 2];
            const float sqq = qm[(i0 + u) * 4 + 3];
            float tmax = -INFINITY;
#pragma unroll
            for (int v = 0; v < 8; v++) {
                float cross = pq0 * km[(j0 + v) * 4 + 0] + pq1 * km[(j0 + v) * 4 + 1] +
                              pq2 * km[(j0 + v) * 4 + 2];
                float sv = s[u][v] * 0.125f + sqq + km[(j0 + v) * 4 + 3] - 2.f * cross;
                if (kmask[j0 + v] != 0.f) sv = -INFINITY;
                s[u][v] = sv;
                tmax = fmaxf(tmax, sv);
            }
            red[(i0 + u) * 16 + tc] = tmax;
        }
        __syncthreads();
        if (tid < 128) {
            float mn = s_m[tid];
#pragma unroll
            for (int c = 0; c < 16; c++) mn = fmaxf(mn, red[tid * 16 + c]);
            s_mn[tid] = mn;
        }
        __syncthreads();
#pragma unroll
        for (int u = 0; u < 8; u++) {
            float mn = s_mn[i0 + u];
            float ps = 0.f;
            if (mn != -INFINITY) {
#pragma unroll
                for (int v = 0; v < 8; v++) ps += __expf(s[u][v] - mn);
            }
            red[(i0 + u) * 16 + tc] = ps;
        }
        __syncthreads();
        if (tid < 128) {
            float mo = s_m[tid], mn = s_mn[tid];
            float l = s_l[tid];
            float scale = (mo == -INFINITY) ? 0.f : __expf(mo - mn);
            l *= scale;
#pragma unroll
            for (int c = 0; c < 16; c++) l += red[tid * 16 + c];
            s_l[tid] = l;
            s_m[tid] = mn;
        }
    }
    __syncthreads();
    if (tid < 128) {
        g_m[(size_t)h * NSEQ + q0 + tid] = s_m[tid];
        g_l[(size_t)h * NSEQ + q0 + tid] = s_l[tid];
    }
}

// ---------------- attention pass 2: normalized w -> g_W, attended = w@V ----------------
__global__ void attn_pass2(const unsigned char* __restrict__ mask) {
    extern __shared__ float sm[];
    float* Qs = sm;                    // 64*129 = 8256
    float* Ks = Qs + 8256;             // 8256
    float* Vs = Ks + 8256;             // 128*68 = 8704
    float* Ps = Vs + 8704;             // 128*129 = 16512
    float* qm = Ps + 16512;            // 512
    float* km = qm + 512;              // 512
    float* kmask = km + 512;           // 128
    float* s_m = kmask + 128;          // 128
    float* s_li = s_m + 128;           // 128

    const int q0 = blockIdx.x * 128;
    const int h = blockIdx.y;
    const int tid = threadIdx.x;
    const int tr = tid / 16, tc = tid % 16;
    const int i0 = tr * 8, j0 = tc * 8;
    const int ib0 = tr * 8, d0 = tc * 4;  // AV roles

    const float* Qg = g_Q + ((size_t)h * NSEQ + q0) * HDIM;
    for (int idx = tid; idx < 128 * 64; idx += 256) {
        int d = idx & 63, i = idx >> 6;
        Qs[d * 129 + i] = Qg[(size_t)i * HDIM + d];
    }
    if (tid < 128) {
        int n = q0 + tid;
        const float* p = g_pq + ((size_t)h * NSEQ + n) * 3;
        qm[tid * 4 + 0] = p[0];
        qm[tid * 4 + 1] = p[1];
        qm[tid * 4 + 2] = p[2];
        qm[tid * 4 + 3] = g_sqq[(size_t)h * NSEQ + n];
        s_m[tid] = g_m[(size_t)h * NSEQ + n];
        float l = g_l[(size_t)h * NSEQ + n];
        s_li[tid] = (l > 0.f) ? 1.f / l : 0.f;
    }

    float acc[8][4];
#pragma unroll
    for (int u = 0; u < 8; u++)
#pragma unroll
        for (int c = 0; c < 4; c++) acc[u][c] = 0.f;

    for (int k0 = 0; k0 < NSEQ; k0 += 128) {
        __syncthreads();  // previous AV reads done
        const float* Kg = g_K + ((size_t)h * NSEQ + k0) * HDIM;
        const float* Vg = g_V + ((size_t)h * NSEQ + k0) * HDIM;
        for (int idx = tid; idx < 128 * 64; idx += 256) {
            int d = idx & 63, j = idx >> 6;
            Ks[d * 129 + j] = Kg[(size_t)j * HDIM + d];
            Vs[j * 68 + d] = Vg[(size_t)j * HDIM + d];
        }
        if (tid < 128) {
            int m = k0 + tid;
            const float* p = g_pk + ((size_t)h * NSEQ + m) * 3;
            km[tid * 4 + 0] = p[0];
            km[tid * 4 + 1] = p[1];
            km[tid * 4 + 2] = p[2];
            km[tid * 4 + 3] = g_sqk[(size_t)h * NSEQ + m];
            kmask[tid] = mask[m] ? 1.f : 0.f;
        }
        __syncthreads();

        float s[8][8];
#pragma unroll
        for (int u = 0; u < 8; u++)
#pragma unroll
            for (int v = 0; v < 8; v++) s[u][v] = 0.f;
#pragma unroll 4
        for (int d = 0; d < 64; d++) {
            float a[8], b[8];
#pragma unroll
            for (int u = 0; u < 8; u++) a[u] = Qs[d * 129 + i0 + u];
#pragma unroll
            for (int v = 0; v < 8; v++) b[v] = Ks[d * 129 + j0 + v];
#pragma unroll
            for (int u = 0; u < 8; u++)
#pragma unroll
                for (int v = 0; v < 8; v++) s[u][v] = fmaf(a[u], b[v], s[u][v]);
        }
#pragma unroll
        for (int u = 0; u < 8; u++) {
            const float pq0 = qm[(i0 + u) * 4 + 0];
            const float pq1 = qm[(i0 + u) * 4 + 1];
            const float pq2 = qm[(i0 + u) * 4 + 2];
            const float sqq = qm[(i0 + u) * 4 + 3];
            const float mrow = s_m[i0 + u];
            const float lirow = s_li[i0 + u];
#pragma unroll
            for (int v = 0; v < 8; v++) {
                float cross = pq0 * km[(j0 + v) * 4 + 0] + pq1 * km[(j0 + v) * 4 + 1] +
                              pq2 * km[(j0 + v) * 4 + 2];
                float sv = s[u][v] * 0.125f + sqq + km[(j0 + v) * 4 + 3] - 2.f * cross;
                float P;
                if (kmask[j0 + v] != 0.f || mrow == -INFINITY)
                    P = 0.f;
                else
                    P = __expf(sv - mrow) * lirow;
                Ps[(j0 + v) * 129 + (i0 + u)] = P;
                g_W[((size_t)h * NSEQ + (q0 + i0 + u)) * NSEQ + (k0 + j0 + v)] = P;
            }
        }
        __syncthreads();
        // AV: acc[i][d] += sum_j Ps[j][i] * Vs[j][d]
#pragma unroll 2
        for (int j = 0; j < 128; j++) {
            float4 vv = *(const float4*)&Vs[j * 68 + d0];
#pragma unroll
            for (int u = 0; u < 8; u++) {
                float p = Ps[j * 129 + ib0 + u];
                acc[u][0] = fmaf(p, vv.x, acc[u][0]);
                acc[u][1] = fmaf(p, vv.y, acc[u][1]);
                acc[u][2] = fmaf(p, vv.z, acc[u][2]);
                acc[u][3] = fmaf(p, vv.w, acc[u][3]);
            }
        }
    }
#pragma unroll
    for (int u = 0; u < 8; u++) {
        int n = q0 + ib0 + u;
#pragma unroll
        for (int c = 0; c < 4; c++)
            g_att[(size_t)n * DMODEL + h * HDIM + d0 + c] = acc[u][c];
    }
}

// ---------------- mean over heads of attention weights ----------------
__global__ void meanw_kernel(float* __restrict__ meanw) {
    size_t idx = (size_t)blockIdx.x * blockDim.x + threadIdx.x;
    if (idx < (size_t)NSEQ * NSEQ) {
        float s = 0.f;
#pragma unroll
        for (int h = 0; h < NHEADS; h++) s += g_W[(size_t)h * NSEQ * NSEQ + idx];
        meanw[idx] = s * (1.f / NHEADS);
    }
}

// ---------------- layernorm over g_res ----------------
__global__ void ln_kernel(const float* __restrict__ gamma, const float* __restrict__ beta,
                          float* __restrict__ out) {
    const int n = blockIdx.x;
    const int tid = threadIdx.x;
    __shared__ float sred[256];
    __shared__ float s_mu, s_rstd;
    const float* r = g_res + (size_t)n * DMODEL;
    float v[4];
    float s = 0.f;
#pragma unroll
    for (int k = 0; k < 4; k++) {
        v[k] = r[tid + k * 256];
        s += v[k];
    }
    sred[tid] = s;
    __syncthreads();
    for (int off = 128; off > 0; off >>= 1) {
        if (tid < off) sred[tid] += sred[tid + off];
        __syncthreads();
    }
    if (tid == 0) s_mu = sred[0] * (1.f / DMODEL);
    __syncthreads();
    const float mu = s_mu;
    float s2 = 0.f;
#pragma unroll
    for (int k = 0; k < 4; k++) {
        float d = v[k] - mu;
        s2 += d * d;
    }
    sred[tid] = s2;
    __syncthreads();
    for (int off = 128; off > 0; off >>= 1) {
        if (tid < off) sred[tid] += sred[tid + off];
        __syncthreads();
    }
    if (tid == 0) s_rstd = rsqrtf(sred[0] * (1.f / DMODEL) + 1e-5f);
    __syncthreads();
    const float rstd = s_rstd;
#pragma unroll
    for (int k = 0; k < 4; k++) {
        int c = tid + k * 256;
        out[(size_t)n * DMODEL + c] = (v[k] - mu) * rstd * gamma[c] + beta[c];
    }
}

// ---------------- host ----------------
#define P1_SMEM (20096 * 4)
#define P2_SMEM (43136 * 4)

extern "C" void kernel_launch(void* const* d_in, const int* in_sizes, int n_in,
                              void* d_out, int out_size) {
    const float* x = (const float*)d_in[0];
    // d_in[1] = positions (unused by the reference forward)
    const unsigned char* mask = (const unsigned char*)d_in[2];
    const float* Wqkv = (const float*)d_in[3];
    const float* bqkv = (const float*)d_in[4];
    const float* Wpq = (const float*)d_in[5];
    const float* bpq = (const float*)d_in[6];
    const float* Wpk = (const float*)d_in[7];
    const float* bpk = (const float*)d_in[8];
    const float* Wo = (const float*)d_in[9];
    const float* bo = (const float*)d_in[10];
    const float* gamma = (const float*)d_in[11];
    const float* beta = (const float*)d_in[12];

    float* out = (float*)d_out;
    float* meanw = out + (size_t)NSEQ * DMODEL;

    void* attp = nullptr;
    cudaGetSymbolAddress(&attp, g_att);

    cudaFuncSetAttribute(attn_pass1, cudaFuncAttributeMaxDynamicSharedMemorySize, P1_SMEM);
    cudaFuncSetAttribute(attn_pass2, cudaFuncAttributeMaxDynamicSharedMemorySize, P2_SMEM);

    // 1) fused QKV projection, scattered into per-head Q/K/V
    sgemm128<0><<<dim3(D3 / 128, NSEQ / 128), 256>>>(x, Wqkv, bqkv, nullptr, D3, DMODEL);
    // 2) point projections + squared norms
    point_proj_kernel<<<NSEQ, 128>>>(x, Wpq, bpq, Wpk, bpk);
    // 3) softmax stats
    attn_pass1<<<dim3(NSEQ / 128, NHEADS), 256, P1_SMEM>>>(mask);
    // 4) normalized weights + attended values
    attn_pass2<<<dim3(NSEQ / 128, NHEADS), 256, P2_SMEM>>>(mask);
    // 5) mean over heads -> second output
    meanw_kernel<<<(NSEQ * NSEQ + 255) / 256, 256>>>(meanw);
    // 6) output projection + residual
    sgemm128<1><<<dim3(DMODEL / 128, NSEQ / 128), 256>>>((const float*)attp, Wo, bo, x,
                                                          DMODEL, DMODEL);
    // 7) layernorm -> first output
    ln_kernel<<<NSEQ, 256>>>(gamma, beta, out);
}

// round 7
// speedup vs baseline: 1.4104x; 1.4101x over previous
#include <cuda_runtime.h>
#include <math.h>
#include <float.h>

#define NSEQ 2048
#define DMODEL 1024
#define NHEADS 16
#define HDIM 64
#define D3 3072
#define NN ((size_t)NSEQ * NSEQ)

__device__ float g_Q[NHEADS * NSEQ * HDIM];
__device__ float g_K[NHEADS * NSEQ * HDIM];
__device__ float g_V[NHEADS * NSEQ * HDIM];
__device__ float g_pq[NHEADS * NSEQ * 3];
__device__ float g_pk[NHEADS * NSEQ * 3];
__device__ float g_sqq[NHEADS * NSEQ];
__device__ float g_sqk[NHEADS * NSEQ];
__device__ float g_m[NHEADS * NSEQ];
__device__ float g_li[NHEADS * NSEQ];
__device__ float g_att[NSEQ * DMODEL];
__device__ float g_res[NSEQ * DMODEL];
__device__ float g_W[(size_t)NHEADS * NN];  // raw logits

// ---------------- 128x128x16 SGEMM (verbatim from passing R1) ----------------
template <int MODE>
__global__ void sgemm128(const float* __restrict__ A, const float* __restrict__ B,
                         const float* __restrict__ bias, const float* __restrict__ resid,
                         int Ncols, int K) {
    __shared__ float As[16][128];
    __shared__ float Bs[16][128];
    const int row0 = blockIdx.y * 128, col0 = blockIdx.x * 128;
    const int tid = threadIdx.x, tr = tid / 16, tc = tid % 16;
    float acc[8][8];
#pragma unroll
    for (int u = 0; u < 8; u++)
#pragma unroll
        for (int v = 0; v < 8; v++) acc[u][v] = 0.f;
    for (int k0 = 0; k0 < K; k0 += 16) {
#pragma unroll
        for (int r = 0; r < 2; r++) {
            int idx = tid + r * 256;
            int ar = idx >> 2, k4 = idx & 3;
            float4 v = *(const float4*)(A + (size_t)(row0 + ar) * K + k0 + k4 * 4);
            As[k4 * 4 + 0][ar] = v.x;
            As[k4 * 4 + 1][ar] = v.y;
            As[k4 * 4 + 2][ar] = v.z;
            As[k4 * 4 + 3][ar] = v.w;
        }
#pragma unroll
        for (int r = 0; r < 2; r++) {
            int idx = tid + r * 256;
            int kk = idx >> 5, j4 = idx & 31;
            *(float4*)(&Bs[kk][j4 * 4]) =
                *(const float4*)(B + (size_t)(k0 + kk) * Ncols + col0 + j4 * 4);
        }
        __syncthreads();
#pragma unroll
        for (int kk = 0; kk < 16; kk++) {
            float a[8], b[8];
#pragma unroll
            for (int u = 0; u < 8; u++) a[u] = As[kk][tr * 8 + u];
#pragma unroll
            for (int v = 0; v < 8; v++) b[v] = Bs[kk][tc * 8 + v];
#pragma unroll
            for (int u = 0; u < 8; u++)
#pragma unroll
                for (int v = 0; v < 8; v++) acc[u][v] = fmaf(a[u], b[v], acc[u][v]);
        }
        __syncthreads();
    }
#pragma unroll
    for (int u = 0; u < 8; u++) {
        int n = row0 + tr * 8 + u;
#pragma unroll
        for (int v = 0; v < 8; v++) {
            int c = col0 + tc * 8 + v;
            float val = acc[u][v] + bias[c];
            if (MODE == 0) {
                int which = c >> 10, h = (c >> 6) & 15, d = c & 63;
                float* dst = (which == 0) ? g_Q : (which == 1) ? g_K : g_V;
                dst[((size_t)h * NSEQ + n) * HDIM + d] = val;
            } else {
                g_res[(size_t)n * DMODEL + c] = val + resid[(size_t)n * DMODEL + c];
            }
        }
    }
}

// ---------------- point projections (verbatim R1) ----------------
__global__ void point_proj_kernel(const float* __restrict__ x, const float* __restrict__ Wpq,
                                  const float* __restrict__ bpq, const float* __restrict__ Wpk,
                                  const float* __restrict__ bpk) {
    __shared__ float xs[DMODEL];
    __shared__ float outs[96];
    const int n = blockIdx.x;
    for (int i = threadIdx.x; i < DMODEL; i += blockDim.x) xs[i] = x[(size_t)n * DMODEL + i];
    __syncthreads();
    const int t = threadIdx.x;
    if (t < 96) {
        const bool isq = t < 48;
        const int c = isq ? t : t - 48;
        const float* W = isq ? Wpq : Wpk;
        float s = isq ? bpq[c] : bpk[c];
#pragma unroll 8
        for (int k = 0; k < DMODEL; k++) s = fmaf(xs[k], W[k * 48 + c], s);
        outs[t] = s;
        (isq ? g_pq : g_pk)[((size_t)(c / 3) * NSEQ + n) * 3 + c % 3] = s;
    }
    __syncthreads();
    if (t < 32) {
        int h = t & 15;
        const float* s = (t < 16) ? outs : outs + 48;
        float a = s[h * 3], b = s[h * 3 + 1], cc = s[h * 3 + 2];
        ((t < 16) ? g_sqq : g_sqk)[(size_t)h * NSEQ + n] = a * a + b * b + cc * cc;
    }
}

// ---------------- single-pass flash attention ----------------
// smem float offsets
#define O_QS 0
#define O_KS 8256
#define O_VS 16512
#define O_PS 25216
#define O_QM 41728
#define O_KM 42240
#define O_MS 42752
#define O_RED 42880
#define O_SM 44928
#define O_SL 45056
#define O_MN 45184
#define O_AL 45312
#define O_LI 45440
#define FL_FLOATS 45568
#define FL_SMEM (FL_FLOATS * 4)

__global__ void flash_attn(const unsigned char* __restrict__ mask) {
    extern __shared__ float sm[];
    float* Qs = sm + O_QS;      // [64][129] transposed
    float* Ks = sm + O_KS;      // [64][129]
    float* Vs = sm + O_VS;      // [128][68]
    float* Ps = sm + O_PS;      // [128][129] P transposed [j][i]
    float* qm = sm + O_QM;      // [128][4]
    float* km = sm + O_KM;      // [128][4]
    float* kmask = sm + O_MS;   // [128]
    float* red = sm + O_RED;    // [128][16]
    float* s_m = sm + O_SM;
    float* s_l = sm + O_SL;
    float* s_mn = sm + O_MN;
    float* s_al = sm + O_AL;
    float* s_li = sm + O_LI;

    const int q0 = blockIdx.x * 128, h = blockIdx.y;
    const int tid = threadIdx.x, tr = tid / 16, tc = tid % 16;
    const int i0 = tr * 8, j0 = tc * 8;
    const int d0 = tc * 4;  // AV col role

    const float* Qg = g_Q + ((size_t)h * NSEQ + q0) * HDIM;
    for (int idx = tid; idx < 128 * 64; idx += 256) {
        int d = idx & 63, i = idx >> 6;
        Qs[d * 129 + i] = Qg[(size_t)i * HDIM + d];
    }
    if (tid < 128) {
        int n = q0 + tid;
        const float* p = g_pq + ((size_t)h * NSEQ + n) * 3;
        qm[tid * 4 + 0] = p[0];
        qm[tid * 4 + 1] = p[1];
        qm[tid * 4 + 2] = p[2];
        qm[tid * 4 + 3] = g_sqq[(size_t)h * NSEQ + n];
        s_m[tid] = -INFINITY;
        s_l[tid] = 0.f;
    }
    float acc[8][4];
#pragma unroll
    for (int u = 0; u < 8; u++)
#pragma unroll
        for (int c = 0; c < 4; c++) acc[u][c] = 0.f;

    for (int k0 = 0; k0 < NSEQ; k0 += 128) {
        __syncthreads();
        const float* Kg = g_K + ((size_t)h * NSEQ + k0) * HDIM;
        const float* Vg = g_V + ((size_t)h * NSEQ + k0) * HDIM;
        for (int idx = tid; idx < 128 * 64; idx += 256) {
            int d = idx & 63, j = idx >> 6;
            Ks[d * 129 + j] = Kg[(size_t)j * HDIM + d];
            Vs[j * 68 + d] = Vg[(size_t)j * HDIM + d];
        }
        if (tid < 128) {
            int m = k0 + tid;
            const float* p = g_pk + ((size_t)h * NSEQ + m) * 3;
            km[tid * 4 + 0] = p[0];
            km[tid * 4 + 1] = p[1];
            km[tid * 4 + 2] = p[2];
            km[tid * 4 + 3] = g_sqk[(size_t)h * NSEQ + m];
            kmask[tid] = mask[m] ? 1.f : 0.f;
        }
        __syncthreads();

        float s[8][8];
#pragma unroll
        for (int u = 0; u < 8; u++)
#pragma unroll
            for (int v = 0; v < 8; v++) s[u][v] = 0.f;
#pragma unroll 4
        for (int d = 0; d < 64; d++) {
            float a[8], b[8];
#pragma unroll
            for (int u = 0; u < 8; u++) a[u] = Qs[d * 129 + i0 + u];
#pragma unroll
            for (int v = 0; v < 8; v++) b[v] = Ks[d * 129 + j0 + v];
#pragma unroll
            for (int u = 0; u < 8; u++)
#pragma unroll
                for (int v = 0; v < 8; v++) s[u][v] = fmaf(a[u], b[v], s[u][v]);
        }
        // point terms + mask; write raw logits; per-thread row max
#pragma unroll
        for (int u = 0; u < 8; u++) {
            const float pq0 = qm[(i0 + u) * 4 + 0];
            const float pq1 = qm[(i0 + u) * 4 + 1];
            const float pq2 = qm[(i0 + u) * 4 + 2];
            const float sqq = qm[(i0 + u) * 4 + 3];
            float tmax = -INFINITY;
            float* Wr = g_W + ((size_t)h * NSEQ + q0 + i0 + u) * NSEQ + k0 + j0;
#pragma unroll
            for (int v = 0; v < 8; v++) {
                float cross = pq0 * km[(j0 + v) * 4 + 0] + pq1 * km[(j0 + v) * 4 + 1] +
                              pq2 * km[(j0 + v) * 4 + 2];
                float sv = s[u][v] * 0.125f + sqq + km[(j0 + v) * 4 + 3] - 2.f * cross;
                if (kmask[j0 + v] != 0.f) sv = -INFINITY;
                s[u][v] = sv;
                Wr[v] = sv;
                tmax = fmaxf(tmax, sv);
            }
            red[(i0 + u) * 16 + tc] = tmax;
        }
        __syncthreads();
        if (tid < 128) {
            float mo = s_m[tid], mn = mo;
#pragma unroll
            for (int c = 0; c < 16; c++) mn = fmaxf(mn, red[tid * 16 + c]);
            s_mn[tid] = mn;
            s_al[tid] = (mo == -INFINITY) ? 0.f : __expf(mo - mn);
            s_m[tid] = mn;
        }
        __syncthreads();
#pragma unroll
        for (int u = 0; u < 8; u++) {
            float mn = s_mn[i0 + u];
            float ps = 0.f;
#pragma unroll
            for (int v = 0; v < 8; v++) {
                float p = (mn == -INFINITY) ? 0.f : __expf(s[u][v] - mn);
                Ps[(j0 + v) * 129 + (i0 + u)] = p;
                ps += p;
            }
            red[(i0 + u) * 16 + tc] = ps;
        }
        __syncthreads();
        if (tid < 128) {
            float l = s_l[tid] * s_al[tid];
#pragma unroll
            for (int c = 0; c < 16; c++) l += red[tid * 16 + c];
            s_l[tid] = l;
        }
        // AV with rescale: rows of this thread are i0+u
        float al[8];
#pragma unroll
        for (int u = 0; u < 8; u++) al[u] = s_al[i0 + u];
#pragma unroll
        for (int u = 0; u < 8; u++)
#pragma unroll
            for (int c = 0; c < 4; c++) acc[u][c] *= al[u];
#pragma unroll 2
        for (int j = 0; j < 128; j++) {
            float4 vv = *(const float4*)&Vs[j * 68 + d0];
#pragma unroll
            for (int u = 0; u < 8; u++) {
                float p = Ps[j * 129 + i0 + u];
                acc[u][0] = fmaf(p, vv.x, acc[u][0]);
                acc[u][1] = fmaf(p, vv.y, acc[u][1]);
                acc[u][2] = fmaf(p, vv.z, acc[u][2]);
                acc[u][3] = fmaf(p, vv.w, acc[u][3]);
            }
        }
    }
    __syncthreads();
    if (tid < 128) {
        float l = s_l[tid];
        float li = (l > 0.f) ? 1.f / l : 0.f;
        s_li[tid] = li;
        g_m[(size_t)h * NSEQ + q0 + tid] = s_m[tid];
        g_li[(size_t)h * NSEQ + q0 + tid] = li;
    }
    __syncthreads();
#pragma unroll
    for (int u = 0; u < 8; u++) {
        int n = q0 + i0 + u;
        float li = s_li[i0 + u];
#pragma unroll
        for (int c = 0; c < 4; c++)
            g_att[(size_t)n * DMODEL + h * HDIM + d0 + c] = acc[u][c] * li;
    }
}

// ---------------- meanw from raw logits ----------------
__global__ void meanw_kernel(float* __restrict__ mw) {
    size_t base = ((size_t)blockIdx.x * 256 + threadIdx.x) * 4;
    int n = (int)(base >> 11);
    float a0 = 0.f, a1 = 0.f, a2 = 0.f, a3 = 0.f;
#pragma unroll
    for (int h = 0; h < NHEADS; h++) {
        float m = g_m[(size_t)h * NSEQ + n];
        float li = g_li[(size_t)h * NSEQ + n];
        float4 s4 = *(const float4*)(g_W + (size_t)h * NN + base);
        if (li > 0.f) {
            a0 += __expf(s4.x - m) * li;
            a1 += __expf(s4.y - m) * li;
            a2 += __expf(s4.z - m) * li;
            a3 += __expf(s4.w - m) * li;
        }
    }
    const float iv = 1.f / NHEADS;
    *(float4*)(mw + base) = make_float4(a0 * iv, a1 * iv, a2 * iv, a3 * iv);
}

// ---------------- layernorm (verbatim R1) ----------------
__global__ void ln_kernel(const float* __restrict__ gamma, const float* __restrict__ beta,
                          float* __restrict__ out) {
    const int n = blockIdx.x, tid = threadIdx.x;
    __shared__ float sr[256];
    __shared__ float s_mu, s_rs;
    const float* r = g_res + (size_t)n * DMODEL;
    float v[4], s = 0.f;
#pragma unroll
    for (int k = 0; k < 4; k++) {
        v[k] = r[tid + k * 256];
        s += v[k];
    }
    sr[tid] = s;
    __syncthreads();
    for (int o = 128; o; o >>= 1) {
        if (tid < o) sr[tid] += sr[tid + o];
        __syncthreads();
    }
    if (tid == 0) s_mu = sr[0] * (1.f / DMODEL);
    __syncthreads();
    float mu = s_mu, s2 = 0.f;
#pragma unroll
    for (int k = 0; k < 4; k++) {
        float d = v[k] - mu;
        s2 += d * d;
    }
    sr[tid] = s2;
    __syncthreads();
    for (int o = 128; o; o >>= 1) {
        if (tid < o) sr[tid] += sr[tid + o];
        __syncthreads();
    }
    if (tid == 0) s_rs = rsqrtf(sr[0] * (1.f / DMODEL) + 1e-5f);
    __syncthreads();
    float rs = s_rs;
#pragma unroll
    for (int k = 0; k < 4; k++) {
        int c = tid + k * 256;
        out[(size_t)n * DMODEL + c] = (v[k] - mu) * rs * gamma[c] + beta[c];
    }
}

extern "C" void kernel_launch(void* const* d_in, const int* in_sizes, int n_in, void* d_out,
                              int out_size) {
    const float* x = (const float*)d_in[0];
    const unsigned char* mask = (const unsigned char*)d_in[2];
    const float* Wqkv = (const float*)d_in[3];
    const float* bqkv = (const float*)d_in[4];
    const float* Wpq = (const float*)d_in[5];
    const float* bpq = (const float*)d_in[6];
    const float* Wpk = (const float*)d_in[7];
    const float* bpk = (const float*)d_in[8];
    const float* Wo = (const float*)d_in[9];
    const float* bo = (const float*)d_in[10];
    const float* gamma = (const float*)d_in[11];
    const float* beta = (const float*)d_in[12];
    float* out = (float*)d_out;
    float* meanw = out + (size_t)NSEQ * DMODEL;

    void* attp = nullptr;
    cudaGetSymbolAddress(&attp, g_att);
    cudaFuncSetAttribute(flash_attn, cudaFuncAttributeMaxDynamicSharedMemorySize, FL_SMEM);

    sgemm128<0><<<dim3(D3 / 128, NSEQ / 128), 256>>>(x, Wqkv, bqkv, nullptr, D3, DMODEL);
    point_proj_kernel<<<NSEQ, 128>>>(x, Wpq, bpq, Wpk, bpk);
    flash_attn<<<dim3(NSEQ / 128, NHEADS), 256, FL_SMEM>>>(mask);
    meanw_kernel<<<NN / 1024, 256>>>(meanw);
    sgemm128<1><<<dim3(DMODEL / 128, NSEQ / 128), 256>>>((const float*)attp, Wo, bo, x, DMODEL,
                                                         DMODEL);
    ln_kernel<<<NSEQ, 256>>>(gamma, beta, out);
}